// round 13
// baseline (speedup 1.0000x reference)
#include <cuda_runtime.h>
#include <cuda_bf16.h>

// GraphConv: out[c] = b + sum_{e:(r,c)} 1/sqrt(d[c]*d[r]) * (x[r] @ W^T)
// R13 = identical resubmit of R8..R12 (broker/container infra failures;
// design unmeasured; precedent: R4's "failed" source passed unchanged in R7
// at 109.2us). Scan removed (bump-allocator bucket bases), int4-vectorized
// edge passes. 5 launches: init, deg, off, place, gather.

#define NMAX 50000
#define EMAX 800000
#define F 64

__device__ float  g_xw[(size_t)NMAX * F];   // x @ W^T
__device__ int    g_deg[NMAX];              // destination degrees
__device__ float  g_rsq[NMAX];              // rsqrt(deg) or 0
__device__ int    g_off[NMAX];              // bucket base (order-free)
__device__ int    g_cnt[NMAX];              // placement cursors
__device__ int    g_total;                  // bump allocator for buckets
__device__ float2 g_edge[EMAX];             // dest-bucketed (src_as_float, val)

// ---------------------------------------------------------------------------
// K0: xw = x @ W^T; zero deg + cnt + total. 256 thr = 32 rows, 8 out/thread.
// ---------------------------------------------------------------------------
__global__ __launch_bounds__(256) void k_init(const float* __restrict__ x,
                       const float* __restrict__ Ww, int n) {
    __shared__ float sWt[F * 68];
    __shared__ float sx [32 * 68];

    for (int i = threadIdx.x; i < F * F; i += 256) {
        int j = i >> 6, k = i & (F - 1);
        sWt[k * 68 + j] = Ww[i];
    }

    int gtid = blockIdx.x * 256 + threadIdx.x;
    if (gtid < n) { g_deg[gtid] = 0; g_cnt[gtid] = 0; }
    if (gtid == 0) g_total = 0;

    int row0 = blockIdx.x * 32;
#pragma unroll
    for (int u = 0; u < 8; u++) {
        int i = threadIdx.x + u * 256;
        int r = i >> 6, k = i & (F - 1);
        float v = (row0 + r < n) ? x[(size_t)(row0 + r) * F + k] : 0.f;
        sx[r * 68 + k] = v;
    }
    __syncthreads();

    int rloc = threadIdx.x >> 3;
    int tj   = threadIdx.x & 7;
    int row  = row0 + rloc;

    float acc[8];
#pragma unroll
    for (int u = 0; u < 8; u++) acc[u] = 0.f;

    const float* wp = sWt + tj * 8;
    const float* xp = sx + rloc * 68;
#pragma unroll
    for (int k = 0; k < F; k += 4) {
        float4 xv = *(const float4*)(xp + k);
#pragma unroll
        for (int kk = 0; kk < 4; kk++) {
            float xs = (kk == 0) ? xv.x : (kk == 1) ? xv.y : (kk == 2) ? xv.z : xv.w;
            float4 w0 = *(const float4*)(wp + (k + kk) * 68);
            float4 w1 = *(const float4*)(wp + (k + kk) * 68 + 4);
            acc[0] = fmaf(xs, w0.x, acc[0]);  acc[1] = fmaf(xs, w0.y, acc[1]);
            acc[2] = fmaf(xs, w0.z, acc[2]);  acc[3] = fmaf(xs, w0.w, acc[3]);
            acc[4] = fmaf(xs, w1.x, acc[4]);  acc[5] = fmaf(xs, w1.y, acc[5]);
            acc[6] = fmaf(xs, w1.z, acc[6]);  acc[7] = fmaf(xs, w1.w, acc[7]);
        }
    }

    if (row < n) {
        size_t base = (size_t)row * F + tj * 8;
        *(float4*)(g_xw + base)     = make_float4(acc[0], acc[1], acc[2], acc[3]);
        *(float4*)(g_xw + base + 4) = make_float4(acc[4], acc[5], acc[6], acc[7]);
    }
}

// ---------------------------------------------------------------------------
// K1: destination-degree histogram, 4 edges/thread (int4 on col half)
// ---------------------------------------------------------------------------
__global__ void k_deg(const int* __restrict__ ei, int E) {
    int t  = blockIdx.x * blockDim.x + threadIdx.x;
    int e4 = t << 2;
    if (e4 + 3 < E) {
        int4 c = *(const int4*)(ei + (size_t)E + e4);
        atomicAdd(&g_deg[c.x], 1);
        atomicAdd(&g_deg[c.y], 1);
        atomicAdd(&g_deg[c.z], 1);
        atomicAdd(&g_deg[c.w], 1);
    } else {
        for (int e = e4; e < E; e++) atomicAdd(&g_deg[__ldg(ei + (size_t)E + e)], 1);
    }
}

// ---------------------------------------------------------------------------
// K2: bucket base via bump allocator (order-free; buckets disjoint) + rsq
// ---------------------------------------------------------------------------
__global__ void k_off(int n) {
    int i = blockIdx.x * blockDim.x + threadIdx.x;
    if (i >= n) return;
    int d = g_deg[i];
    g_off[i] = (d > 0) ? atomicAdd(&g_total, d) : 0;
    g_rsq[i] = (d > 0) ? rsqrtf((float)d) : 0.f;
}

// ---------------------------------------------------------------------------
// K3: place edges into destination buckets, 4 edges/thread
// ---------------------------------------------------------------------------
__global__ void k_place(const int* __restrict__ ei, int E) {
    int t  = blockIdx.x * blockDim.x + threadIdx.x;
    int e4 = t << 2;
    if (e4 + 3 < E) {
        int4 r = *(const int4*)(ei + e4);
        int4 c = *(const int4*)(ei + (size_t)E + e4);
#pragma unroll
        for (int u = 0; u < 4; u++) {
            int rr = (u == 0) ? r.x : (u == 1) ? r.y : (u == 2) ? r.z : r.w;
            int cc = (u == 0) ? c.x : (u == 1) ? c.y : (u == 2) ? c.z : c.w;
            float v = g_rsq[rr] * g_rsq[cc];
            int pos = g_off[cc] + atomicAdd(&g_cnt[cc], 1);
            g_edge[pos] = make_float2(__int_as_float(rr), v);
        }
    } else {
        for (int e = e4; e < E; e++) {
            int rr = __ldg(ei + e);
            int cc = __ldg(ei + (size_t)E + e);
            float v = g_rsq[rr] * g_rsq[cc];
            int pos = g_off[cc] + atomicAdd(&g_cnt[cc], 1);
            g_edge[pos] = make_float2(__int_as_float(rr), v);
        }
    }
}

// ---------------------------------------------------------------------------
// K4: pull-mode gather. 2 nodes/warp, 16 lanes x float4 = 256B row.
// Batch 16 edge records per half-warp, broadcast via width-16 shfl.
// out[c] = bias + sum v * xw[r]. No float atomics.
// ---------------------------------------------------------------------------
__global__ __launch_bounds__(256) void k_gather(const float* __restrict__ Wb,
                                                float* __restrict__ out, int n) {
    int idx  = blockIdx.x * 256 + threadIdx.x;
    int sub  = (idx >> 4) & 1;                 // half-warp id
    int l16  = idx & 15;
    int c    = ((idx >> 5) << 1) + sub;        // node (uniform per half-warp)
    if (c >= n) return;
    unsigned hm = 0xFFFFu << (sub << 4);       // half-warp mask

    int off = g_off[c];
    int dc  = g_deg[c];

    float4 acc = __ldg((const float4*)Wb + l16);   // bias

    for (int base = 0; base < dc; base += 16) {
        int j = base + l16;
        float2 ev = (j < dc) ? __ldg(g_edge + off + j) : make_float2(0.f, 0.f);
        int cnt = dc - base; if (cnt > 16) cnt = 16;
#pragma unroll 4
        for (int t = 0; t < cnt; t++) {
            int   rt = __shfl_sync(hm, __float_as_int(ev.x), t, 16);
            float vt = __shfl_sync(hm, ev.y, t, 16);
            float4 m = __ldg((const float4*)(g_xw + ((size_t)rt << 6)) + l16);
            acc.x = fmaf(vt, m.x, acc.x);
            acc.y = fmaf(vt, m.y, acc.y);
            acc.z = fmaf(vt, m.z, acc.z);
            acc.w = fmaf(vt, m.w, acc.w);
        }
    }

    ((float4*)(out + ((size_t)c << 6)))[l16] = acc;
}

extern "C" void kernel_launch(void* const* d_in, const int* in_sizes, int n_in,
                              void* d_out, int out_size) {
    const float* x  = (const float*)d_in[0];
    // d_in[1] = x0, unused (use_init=False)
    const int*   ei = (const int*)d_in[2];    // int32 (JAX x64 disabled)
    const float* Ww = (const float*)d_in[3];
    const float* Wb = (const float*)d_in[4];
    float*       out = (float*)d_out;

    int n = in_sizes[0] / F;                  // 50000
    int E = in_sizes[2] / 2;                  // 800000

    int e4 = (E + 3) / 4;                     // threads for 4-edge kernels

    k_init <<<(n + 31) / 32, 256>>>(x, Ww, n);
    k_deg  <<<(e4 + 255) / 256, 256>>>(ei, E);
    k_off  <<<(n + 255) / 256, 256>>>(n);
    k_place<<<(e4 + 255) / 256, 256>>>(ei, E);
    k_gather<<<(n + 15) / 16, 256>>>(Wb, out, n);
}

// round 17
// speedup vs baseline: 1.5196x; 1.5196x over previous
#include <cuda_runtime.h>
#include <cuda_bf16.h>

// GraphConv: out[c] = b + sum_{e:(r,c)} 1/sqrt(d[c]*d[r]) * (x[r] @ W^T)
// R17 = identical resubmit of R14/R15/R16 (broker timeouts). R13 measured
// the int4 4-edge/thread experiment as a REGRESSION (k_place 29us @ 2.9%
// issue): atomic-latency-bound passes need max thread-count, not per-thread
// batching. This source = R7-measured-good edge passes (1 edge/thread) +
// bump-allocator k_off (replaces measured 5.1us serial scan). 5 launches.

#define NMAX 50000
#define EMAX 800000
#define F 64

__device__ float  g_xw[(size_t)NMAX * F];   // x @ W^T
__device__ int    g_deg[NMAX];              // destination degrees
__device__ float  g_rsq[NMAX];              // rsqrt(deg) or 0
__device__ int    g_off[NMAX];              // bucket base (order-free)
__device__ int    g_cnt[NMAX];              // placement cursors
__device__ int    g_total;                  // bump allocator for buckets
__device__ float2 g_edge[EMAX];             // dest-bucketed (src_as_float, val)

// ---------------------------------------------------------------------------
// K0: xw = x @ W^T; zero deg + cnt + total. 256 thr = 32 rows, 8 out/thread.
// ---------------------------------------------------------------------------
__global__ __launch_bounds__(256) void k_init(const float* __restrict__ x,
                       const float* __restrict__ Ww, int n) {
    __shared__ float sWt[F * 68];
    __shared__ float sx [32 * 68];

    for (int i = threadIdx.x; i < F * F; i += 256) {
        int j = i >> 6, k = i & (F - 1);
        sWt[k * 68 + j] = Ww[i];
    }

    int gtid = blockIdx.x * 256 + threadIdx.x;
    if (gtid < n) { g_deg[gtid] = 0; g_cnt[gtid] = 0; }
    if (gtid == 0) g_total = 0;

    int row0 = blockIdx.x * 32;
#pragma unroll
    for (int u = 0; u < 8; u++) {
        int i = threadIdx.x + u * 256;
        int r = i >> 6, k = i & (F - 1);
        float v = (row0 + r < n) ? x[(size_t)(row0 + r) * F + k] : 0.f;
        sx[r * 68 + k] = v;
    }
    __syncthreads();

    int rloc = threadIdx.x >> 3;
    int tj   = threadIdx.x & 7;
    int row  = row0 + rloc;

    float acc[8];
#pragma unroll
    for (int u = 0; u < 8; u++) acc[u] = 0.f;

    const float* wp = sWt + tj * 8;
    const float* xp = sx + rloc * 68;
#pragma unroll
    for (int k = 0; k < F; k += 4) {
        float4 xv = *(const float4*)(xp + k);
#pragma unroll
        for (int kk = 0; kk < 4; kk++) {
            float xs = (kk == 0) ? xv.x : (kk == 1) ? xv.y : (kk == 2) ? xv.z : xv.w;
            float4 w0 = *(const float4*)(wp + (k + kk) * 68);
            float4 w1 = *(const float4*)(wp + (k + kk) * 68 + 4);
            acc[0] = fmaf(xs, w0.x, acc[0]);  acc[1] = fmaf(xs, w0.y, acc[1]);
            acc[2] = fmaf(xs, w0.z, acc[2]);  acc[3] = fmaf(xs, w0.w, acc[3]);
            acc[4] = fmaf(xs, w1.x, acc[4]);  acc[5] = fmaf(xs, w1.y, acc[5]);
            acc[6] = fmaf(xs, w1.z, acc[6]);  acc[7] = fmaf(xs, w1.w, acc[7]);
        }
    }

    if (row < n) {
        size_t base = (size_t)row * F + tj * 8;
        *(float4*)(g_xw + base)     = make_float4(acc[0], acc[1], acc[2], acc[3]);
        *(float4*)(g_xw + base + 4) = make_float4(acc[4], acc[5], acc[6], acc[7]);
    }
}

// ---------------------------------------------------------------------------
// K1: destination-degree histogram, 1 edge/thread (max atomic MLP)
// ---------------------------------------------------------------------------
__global__ void k_deg(const int* __restrict__ ei, int E) {
    int e = blockIdx.x * blockDim.x + threadIdx.x;
    if (e < E) atomicAdd(&g_deg[__ldg(ei + (size_t)E + e)], 1);
}

// ---------------------------------------------------------------------------
// K2: bucket base via bump allocator (order-free; buckets disjoint) + rsq
// ---------------------------------------------------------------------------
__global__ void k_off(int n) {
    int i = blockIdx.x * blockDim.x + threadIdx.x;
    if (i >= n) return;
    int d = g_deg[i];
    g_off[i] = (d > 0) ? atomicAdd(&g_total, d) : 0;
    g_rsq[i] = (d > 0) ? rsqrtf((float)d) : 0.f;
}

// ---------------------------------------------------------------------------
// K3: place edges into destination buckets, 1 edge/thread (max atomic MLP)
// ---------------------------------------------------------------------------
__global__ void k_place(const int* __restrict__ ei, int E) {
    int e = blockIdx.x * blockDim.x + threadIdx.x;
    if (e >= E) return;
    int r = __ldg(ei + e);
    int c = __ldg(ei + (size_t)E + e);
    float v = g_rsq[r] * g_rsq[c];
    int pos = g_off[c] + atomicAdd(&g_cnt[c], 1);
    g_edge[pos] = make_float2(__int_as_float(r), v);
}

// ---------------------------------------------------------------------------
// K4: pull-mode gather. 2 nodes/warp, 16 lanes x float4 = 256B row.
// Batch 16 edge records per half-warp, broadcast via width-16 shfl.
// out[c] = bias + sum v * xw[r]. No float atomics.
// ---------------------------------------------------------------------------
__global__ __launch_bounds__(256) void k_gather(const float* __restrict__ Wb,
                                                float* __restrict__ out, int n) {
    int idx  = blockIdx.x * 256 + threadIdx.x;
    int sub  = (idx >> 4) & 1;                 // half-warp id
    int l16  = idx & 15;
    int c    = ((idx >> 5) << 1) + sub;        // node (uniform per half-warp)
    if (c >= n) return;
    unsigned hm = 0xFFFFu << (sub << 4);       // half-warp mask

    int off = g_off[c];
    int dc  = g_deg[c];

    float4 acc = __ldg((const float4*)Wb + l16);   // bias

    for (int base = 0; base < dc; base += 16) {
        int j = base + l16;
        float2 ev = (j < dc) ? __ldg(g_edge + off + j) : make_float2(0.f, 0.f);
        int cnt = dc - base; if (cnt > 16) cnt = 16;
#pragma unroll 4
        for (int t = 0; t < cnt; t++) {
            int   rt = __shfl_sync(hm, __float_as_int(ev.x), t, 16);
            float vt = __shfl_sync(hm, ev.y, t, 16);
            float4 m = __ldg((const float4*)(g_xw + ((size_t)rt << 6)) + l16);
            acc.x = fmaf(vt, m.x, acc.x);
            acc.y = fmaf(vt, m.y, acc.y);
            acc.z = fmaf(vt, m.z, acc.z);
            acc.w = fmaf(vt, m.w, acc.w);
        }
    }

    ((float4*)(out + ((size_t)c << 6)))[l16] = acc;
}

extern "C" void kernel_launch(void* const* d_in, const int* in_sizes, int n_in,
                              void* d_out, int out_size) {
    const float* x  = (const float*)d_in[0];
    // d_in[1] = x0, unused (use_init=False)
    const int*   ei = (const int*)d_in[2];    // int32 (JAX x64 disabled)
    const float* Ww = (const float*)d_in[3];
    const float* Wb = (const float*)d_in[4];
    float*       out = (float*)d_out;

    int n = in_sizes[0] / F;                  // 50000
    int E = in_sizes[2] / 2;                  // 800000

    k_init <<<(n + 31) / 32, 256>>>(x, Ww, n);
    k_deg  <<<(E + 255) / 256, 256>>>(ei, E);
    k_off  <<<(n + 255) / 256, 256>>>(n);
    k_place<<<(E + 255) / 256, 256>>>(ei, E);
    k_gather<<<(n + 15) / 16, 256>>>(Wb, out, n);
}